// round 8
// baseline (speedup 1.0000x reference)
#include <cuda_runtime.h>
#include <cuda_fp16.h>
#include <cstdint>

#define Bx 8
#define Dx 128
#define Tx 4096
#define Kx 1024
#define Sx 8
#define ROWS (Bx*Tx)            // 32768
#define NCTAS (ROWS/128)        // 256
#define TAU 0.4f                // rescore window (>> 2*eps_max)

// ---------------- device scratch (no runtime allocation) -------------------
__device__ float g_c2[Sx * Kx];                 // ||c||^2 fp32
__device__ float g_part[Sx * NCTAS];            // commit partials
// fp16 B fragment bundles: per (s,nt) tile: 128 rows x 16 uint4 (256B/row)
__device__ uint4 g_cbB[(size_t)Sx * Kx * 16];   // 2 MB

// ---------------- SMEM layout (byte offsets) --------------------------------
#define BROW    288           // padded B row stride (conflict-free LDS.64)
#define BBUF    36864         // 128 * 288
#define SMB_B   0             // 2 x BBUF = 73728
#define SMB_R   73728         // 128 x 132 fp32 = 67584
#define SMB_C2  141312        // 1024 fp32
#define SMB_T4V 145408        // 128 x 4 fp32
#define SMB_T4I 147456        // 128 x 4 int
#define SMB_IDX 149504        // 128 int
#define SMB_RED 150016        // 256 fp32
#define SMEM_TOTAL 151040

// ---------------- helpers ----------------------------------------------------
__device__ __forceinline__ uint32_t pack_f16(float a, float b) {
    __half2 h = __floats2half2_rn(a, b);      // .x = a (low half)
    return *reinterpret_cast<uint32_t*>(&h);
}
__device__ __forceinline__ uint32_t smem_u32(const void* p) {
    uint32_t a;
    asm("{ .reg .u64 t; cvta.to.shared.u64 t, %1; cvt.u32.u64 %0, t; }" : "=r"(a) : "l"(p));
    return a;
}

// m16n8k16 row.col fp16 MMA, fp32 accumulate (in place)
__device__ __forceinline__ void mma_f16(float* c, const uint32_t* a,
                                        uint32_t b0, uint32_t b1) {
    asm volatile(
        "mma.sync.aligned.m16n8k16.row.col.f32.f16.f16.f32 "
        "{%0,%1,%2,%3}, {%4,%5,%6,%7}, {%8,%9}, {%0,%1,%2,%3};"
        : "+f"(c[0]), "+f"(c[1]), "+f"(c[2]), "+f"(c[3])
        : "r"(a[0]), "r"(a[1]), "r"(a[2]), "r"(a[3]), "r"(b0), "r"(b1));
}

#define CP_ASYNC16(dst, src) \
    asm volatile("cp.async.cg.shared.global [%0], [%1], 16;" :: "r"(dst), "l"(src))
#define CP_COMMIT() asm volatile("cp.async.commit_group;" ::: "memory")
#define CP_WAIT0()  asm volatile("cp.async.wait_group 0;" ::: "memory")

// sorted top-4 insert (ascending value; index tie-break -> smaller idx wins)
__device__ __forceinline__ void ins4(float v[4], int id[4], float d, int n) {
    if (d < v[3] || (d == v[3] && n < id[3])) {
        v[3] = d; id[3] = n;
        #pragma unroll
        for (int j = 3; j > 0; j--) {
            bool sw = (v[j] < v[j-1]) || (v[j] == v[j-1] && id[j] < id[j-1]);
            if (sw) {
                float tv = v[j]; v[j] = v[j-1]; v[j-1] = tv;
                int   ti = id[j]; id[j] = id[j-1]; id[j-1] = ti;
            }
        }
    }
}

// ---------------------------------------------------------------------------
// ||c||^2 for all stages: one warp per codeword.
// ---------------------------------------------------------------------------
__global__ void c2_kernel(const float* __restrict__ cb) {
    int w    = (blockIdx.x * blockDim.x + threadIdx.x) >> 5;
    int lane = threadIdx.x & 31;
    if (w >= Sx * Kx) return;
    float4 v = reinterpret_cast<const float4*>(cb)[(size_t)w * 32 + lane];
    float p = v.x * v.x + v.y * v.y + v.z * v.z + v.w * v.w;
    #pragma unroll
    for (int o = 16; o; o >>= 1) p += __shfl_down_sync(0xFFFFFFFFu, p, o);
    if (lane == 0) g_c2[w] = p;
}

// ---------------------------------------------------------------------------
// Codebooks -> fp16 fragment chunks. One thread per 16B chunk (2 bundles).
// idx = gk*16 + kc*2 + tp  (tp selects tig pair {2tp, 2tp+1})
// ---------------------------------------------------------------------------
__global__ void cvt_cb_kernel(const float* __restrict__ cb) {
    int idx = blockIdx.x * 256 + threadIdx.x;
    if (idx >= Sx * Kx * 16) return;
    int tp = idx & 1;
    int kc = (idx >> 1) & 7;
    int gk = idx >> 4;                           // s*Kx + n
    const float* row = cb + (size_t)gk * Dx + kc * 16 + 4 * tp;
    uint4 v;
    v.x = pack_f16(row[0], row[1]);              // tig=2tp,  b0
    v.y = pack_f16(row[8], row[9]);              // tig=2tp,  b1
    v.z = pack_f16(row[2], row[3]);              // tig=2tp+1, b0
    v.w = pack_f16(row[10], row[11]);            // tig=2tp+1, b1
    int s = gk >> 10, n = gk & 1023;
    size_t dst = ((size_t)(s * 8 + (n >> 7)) * 128 + (n & 127)) * 16 + kc * 2 + tp;
    g_cbB[dst] = v;
}

// ---------------------------------------------------------------------------
// Fused 8-stage RVQ: 1-pass fp16 mma + exact top-4 rescore.
// grid = 256 CTAs x 256 threads; warp w owns rows w*16..w*16+15.
// ---------------------------------------------------------------------------
__global__ void __launch_bounds__(256, 1)
rvq_kernel(const float* __restrict__ x, const float* __restrict__ cb,
           float* __restrict__ out) {
    extern __shared__ char sm[];
    float* R_sm = (float*)(sm + SMB_R);
    float* c2s  = (float*)(sm + SMB_C2);
    float* t4v  = (float*)(sm + SMB_T4V);
    int*   t4i  = (int*)(sm + SMB_T4I);
    int*   sidx = (int*)(sm + SMB_IDX);
    float* red  = (float*)(sm + SMB_RED);
    const uint32_t smb = smem_u32(sm);

    const int tid  = threadIdx.x;
    const int wid  = tid >> 5;
    const int lane = tid & 31;
    const int g    = lane >> 2;
    const int tig  = lane & 3;
    const int wrow = wid * 16;
    const int row0 = blockIdx.x * 128;
    const int b    = row0 >> 12;
    const int t0   = row0 & (Tx - 1);
    const size_t QOFF = (size_t)Bx * Dx * Tx;

    // ---- initial residual: R[t][d] = x[b][d][t0+t] (coalesced over t) ----
    #pragma unroll
    for (int it = 0; it < 64; it++) {
        int idx = it * 256 + tid;
        int d = idx >> 7, tl = idx & 127;
        R_sm[tl * 132 + d] = x[((size_t)b * Dx + d) * Tx + t0 + tl];
    }
    __syncthreads();

    #pragma unroll 1
    for (int s = 0; s < Sx; s++) {
        // stage c2 into SMEM
        for (int i = tid; i < Kx; i += 256) c2s[i] = g_c2[s * Kx + i];

        // ---- A fragments: this warp's 16 rows as fp16, reused all nt ----
        uint32_t ah[8][4];
        #pragma unroll
        for (int kc = 0; kc < 8; kc++) {
            const float* base = &R_sm[(wrow + g) * 132 + kc * 16 + 2 * tig];
            float2 p0 = *(const float2*)(base);
            float2 p1 = *(const float2*)(base + 8 * 132);
            float2 p2 = *(const float2*)(base + 8);
            float2 p3 = *(const float2*)(base + 8 * 132 + 8);
            ah[kc][0] = pack_f16(p0.x, p0.y);
            ah[kc][1] = pack_f16(p1.x, p1.y);
            ah[kc][2] = pack_f16(p2.x, p2.y);
            ah[kc][3] = pack_f16(p3.x, p3.y);
        }

        // per-thread exact top-4 for two row-slots (row wrow+g, row wrow+g+8)
        const float INF = __int_as_float(0x7F800000);
        float va[4] = {INF, INF, INF, INF}, vb[4] = {INF, INF, INF, INF};
        int   ia[4] = {0x7fffffff, 0x7fffffff, 0x7fffffff, 0x7fffffff};
        int   ib[4] = {0x7fffffff, 0x7fffffff, 0x7fffffff, 0x7fffffff};

        // ---- prefetch B tile nt=0 into buf 0 ----
        {
            const char* src = (const char*)(g_cbB + (size_t)(s * 8 + 0) * 2048);
            #pragma unroll
            for (int it = 0; it < 8; it++) {
                int idx = it * 256 + tid;
                int r = idx >> 4, c = idx & 15;
                CP_ASYNC16(smb + SMB_B + r * BROW + c * 16, src + r * 256 + c * 16);
            }
            CP_COMMIT();
        }

        #pragma unroll 1
        for (int nt = 0; nt < 8; nt++) {
            CP_WAIT0();
            __syncthreads();                 // B tile(nt) visible to all warps
            if (nt < 7) {                    // prefetch nt+1 into other buffer
                const char* src = (const char*)(g_cbB + (size_t)(s * 8 + nt + 1) * 2048);
                uint32_t dst = smb + SMB_B + ((nt + 1) & 1) * BBUF;
                #pragma unroll
                for (int it = 0; it < 8; it++) {
                    int idx = it * 256 + tid;
                    int r = idx >> 4, c = idx & 15;
                    CP_ASYNC16(dst + r * BROW + c * 16, src + r * 256 + c * 16);
                }
                CP_COMMIT();
            }

            const char* bbase = sm + SMB_B + (nt & 1) * BBUF;
            float acc[64];
            #pragma unroll
            for (int i = 0; i < 64; i++) acc[i] = 0.0f;

            #pragma unroll
            for (int kc = 0; kc < 8; kc++) {
                #pragma unroll
                for (int nb = 0; nb < 16; nb++) {
                    uint2 bv = *(const uint2*)(bbase + (nb * 8 + g) * BROW
                                               + kc * 32 + tig * 8);
                    mma_f16(&acc[nb * 4], ah[kc], bv.x, bv.y);
                }
            }

            // ---- fold distances into per-thread top-4 ----
            #pragma unroll
            for (int nb = 0; nb < 16; nb++) {
                int n0 = nt * 128 + nb * 8 + 2 * tig;
                float2 cc = *(const float2*)&c2s[n0];
                float d0 = fmaf(-2.0f, acc[nb * 4 + 0], cc.x);
                float d1 = fmaf(-2.0f, acc[nb * 4 + 1], cc.y);
                float d2 = fmaf(-2.0f, acc[nb * 4 + 2], cc.x);
                float d3 = fmaf(-2.0f, acc[nb * 4 + 3], cc.y);
                ins4(va, ia, d0, n0);
                ins4(va, ia, d1, n0 + 1);
                ins4(vb, ib, d2, n0);
                ins4(vb, ib, d3, n0 + 1);
            }
            // next iteration's __syncthreads (after wait) protects buffer reuse
        }

        // ---- merge top-4 across the 4 tig lanes (exact, tie-aware) ----
        #pragma unroll
        for (int off = 1; off <= 2; off <<= 1) {
            float wv[4]; int wi[4];
            #pragma unroll
            for (int j = 0; j < 4; j++) {
                wv[j] = __shfl_xor_sync(0xFFFFFFFFu, va[j], off);
                wi[j] = __shfl_xor_sync(0xFFFFFFFFu, ia[j], off);
            }
            #pragma unroll
            for (int j = 0; j < 4; j++) ins4(va, ia, wv[j], wi[j]);
            #pragma unroll
            for (int j = 0; j < 4; j++) {
                wv[j] = __shfl_xor_sync(0xFFFFFFFFu, vb[j], off);
                wi[j] = __shfl_xor_sync(0xFFFFFFFFu, ib[j], off);
            }
            #pragma unroll
            for (int j = 0; j < 4; j++) ins4(vb, ib, wv[j], wi[j]);
        }
        if (tig == 0) {
            #pragma unroll
            for (int j = 0; j < 4; j++) {
                t4v[(wrow + g) * 4 + j] = va[j];     t4i[(wrow + g) * 4 + j] = ia[j];
                t4v[(wrow + g + 8) * 4 + j] = vb[j]; t4i[(wrow + g + 8) * 4 + j] = ib[j];
            }
        }
        __syncthreads();

        // ---- pick: exact fp32 rescore of all candidates within TAU ----
        if (tid < 128) {
            float v0 = t4v[tid * 4 + 0];
            int   bi = t4i[tid * 4 + 0];
            if (t4v[tid * 4 + 1] - v0 < TAU) {
                const float* rr = &R_sm[tid * 132];
                float bestd = __int_as_float(0x7F800000);
                int   besti = 0x7fffffff;
                #pragma unroll 1
                for (int j = 0; j < 4; j++) {
                    if (j > 0 && t4v[tid * 4 + j] - v0 >= TAU) break;
                    int k = t4i[tid * 4 + j];
                    const float* cp = cb + ((size_t)s * Kx + k) * Dx;
                    float dot = 0.0f;
                    #pragma unroll 8
                    for (int i = 0; i < Dx; i++) dot = fmaf(rr[i], cp[i], dot);
                    float dex = fmaf(-2.0f, dot, c2s[k]);
                    if (dex < bestd || (dex == bestd && k < besti)) {
                        bestd = dex; besti = k;
                    }
                }
                bi = besti;
            }
            sidx[tid] = bi;
            out[QOFF + (size_t)s * ROWS + row0 + tid] = (float)bi;
        }
        __syncthreads();

        // ---- residual update + commit partial ----
        float cm = 0.0f;
        #pragma unroll
        for (int it = 0; it < 64; it++) {
            int idx = it * 256 + tid;
            int m = idx >> 7, d = idx & 127;
            int k = sidx[m];
            float q  = cb[((size_t)s * Kx + k) * Dx + d];
            float r  = R_sm[m * 132 + d];
            float nr = r - q;
            cm = fmaf(nr, nr, cm);
            R_sm[m * 132 + d] = nr;
        }
        red[tid] = cm;
        __syncthreads();
        #pragma unroll
        for (int st = 128; st > 0; st >>= 1) {
            if (tid < st) red[tid] += red[tid + st];
            __syncthreads();
        }
        if (tid == 0) g_part[s * NCTAS + blockIdx.x] = red[0];
        __syncthreads();
    }

    // ---- quantized output: out[b][d][t] = x - R_final ----
    #pragma unroll
    for (int it = 0; it < 64; it++) {
        int idx = it * 256 + tid;
        int d = idx >> 7, tl = idx & 127;
        size_t go = ((size_t)b * Dx + d) * Tx + t0 + tl;
        out[go] = x[go] - R_sm[tl * 132 + d];
    }
}

// ---------------------------------------------------------------------------
// bw + penalty
// ---------------------------------------------------------------------------
__global__ void pack_kernel(float* __restrict__ out) {
    __shared__ float red[256];
    const size_t COFF = (size_t)Bx * Dx * Tx + (size_t)Sx * ROWS;
    int tid = threadIdx.x;
    float s = 0.0f;
    for (int i = tid; i < Sx * NCTAS; i += 256) s += g_part[i];
    red[tid] = s;
    __syncthreads();
    #pragma unroll
    for (int st = 128; st > 0; st >>= 1) {
        if (tid < st) red[tid] += red[tid + st];
        __syncthreads();
    }
    if (tid == 0) {
        out[COFF + 0] = 6000.0f;   // 8 * log2(1024) * 75
        out[COFF + 1] = red[0] / ((float)Sx * (float)ROWS * (float)Dx);
    }
}

extern "C" void kernel_launch(void* const* d_in, const int* in_sizes, int n_in,
                              void* d_out, int out_size) {
    const float* x  = (const float*)d_in[0];
    const float* cb = (const float*)d_in[1];
    float* out = (float*)d_out;

    cudaFuncSetAttribute(rvq_kernel, cudaFuncAttributeMaxDynamicSharedMemorySize,
                         SMEM_TOTAL);

    c2_kernel<<<(Sx * Kx * 32) / 256, 256>>>(cb);
    cvt_cb_kernel<<<(Sx * Kx * 16) / 256, 256>>>(cb);
    rvq_kernel<<<NCTAS, 256, SMEM_TOTAL>>>(x, cb, out);
    pack_kernel<<<1, 256>>>(out);
}

// round 9
// speedup vs baseline: 2.3860x; 2.3860x over previous
#include <cuda_runtime.h>
#include <cuda_fp16.h>
#include <cstdint>

#define Bx 8
#define Dx 128
#define Tx 4096
#define Kx 1024
#define Sx 8
#define ROWS (Bx*Tx)            // 32768
#define NCTAS (ROWS/128)        // 256
#define TAU 0.25f               // rescore window (>>sigma + key quantization)
#define KEYMASK 0xFFFFFC00u

// ---------------- device scratch (no runtime allocation) -------------------
__device__ float g_c2[Sx * Kx];                 // ||c||^2 fp32
__device__ float g_part[Sx * NCTAS];            // commit partials
// fp16 B fragment bundles: per (s,nt) tile: 128 rows x 16 uint4 (256B/row)
__device__ uint4 g_cbB[(size_t)Sx * Kx * 16];   // 2 MB

// ---------------- SMEM layout (byte offsets) --------------------------------
#define BROW    288           // padded B row stride (conflict-free LDS.64)
#define BBUF    36864         // 128 * 288
#define SMB_B   0             // 2 x BBUF = 73728
#define SMB_R   73728         // 128 x 132 fp32 = 67584
#define SMB_C2  141312        // 1024 fp32
#define SMB_K1  145408        // 128 u32  (best key per row)
#define SMB_K2  145920        // 128 u32  (2nd key per row)
#define SMB_IDX 146432        // 128 int
#define SMB_RED 146944        // 256 fp32
#define SMEM_TOTAL 147968

// ---------------- helpers ----------------------------------------------------
__device__ __forceinline__ uint32_t pack_f16(float a, float b) {
    __half2 h = __floats2half2_rn(a, b);
    return *reinterpret_cast<uint32_t*>(&h);
}
__device__ __forceinline__ uint32_t smem_u32(const void* p) {
    uint32_t a;
    asm("{ .reg .u64 t; cvta.to.shared.u64 t, %1; cvt.u32.u64 %0, t; }" : "=r"(a) : "l"(p));
    return a;
}

// m16n8k16 row.col fp16 MMA, fp32 accumulate (in place)
__device__ __forceinline__ void mma_f16(float* c, const uint32_t* a,
                                        uint32_t b0, uint32_t b1) {
    asm volatile(
        "mma.sync.aligned.m16n8k16.row.col.f32.f16.f16.f32 "
        "{%0,%1,%2,%3}, {%4,%5,%6,%7}, {%8,%9}, {%0,%1,%2,%3};"
        : "+f"(c[0]), "+f"(c[1]), "+f"(c[2]), "+f"(c[3])
        : "r"(a[0]), "r"(a[1]), "r"(a[2]), "r"(a[3]), "r"(b0), "r"(b1));
}

#define CP_ASYNC16(dst, src) \
    asm volatile("cp.async.cg.shared.global [%0], [%1], 16;" :: "r"(dst), "l"(src))
#define CP_COMMIT() asm volatile("cp.async.commit_group;" ::: "memory")
#define CP_WAIT0()  asm volatile("cp.async.wait_group 0;" ::: "memory")

// order-preserving float->uint, low 10 bits replaced by candidate index
__device__ __forceinline__ uint32_t mk_key(float d, int n) {
    uint32_t b = __float_as_uint(d);
    uint32_t u = b ^ ((uint32_t)((int32_t)b >> 31) | 0x80000000u);
    return (u & KEYMASK) | (uint32_t)n;
}
// approximate inverse (low bits zeroed)
__device__ __forceinline__ float key_to_f(uint32_t k) {
    uint32_t u = k & KEYMASK;
    uint32_t b = (u & 0x80000000u) ? (u ^ 0x80000000u) : ~u;
    return __uint_as_float(b);
}
// branchless top-2 key insert (order: v2 before v1!)
__device__ __forceinline__ void ins2(uint32_t& v1, uint32_t& v2, uint32_t k) {
    uint32_t t = v1 > k ? v1 : k;     // max(v1_old, k)
    v2 = v2 < t ? v2 : t;
    v1 = v1 < k ? v1 : k;
}

// ---------------------------------------------------------------------------
// ||c||^2 for all stages: one warp per codeword.
// ---------------------------------------------------------------------------
__global__ void c2_kernel(const float* __restrict__ cb) {
    int w    = (blockIdx.x * blockDim.x + threadIdx.x) >> 5;
    int lane = threadIdx.x & 31;
    if (w >= Sx * Kx) return;
    float4 v = reinterpret_cast<const float4*>(cb)[(size_t)w * 32 + lane];
    float p = v.x * v.x + v.y * v.y + v.z * v.z + v.w * v.w;
    #pragma unroll
    for (int o = 16; o; o >>= 1) p += __shfl_down_sync(0xFFFFFFFFu, p, o);
    if (lane == 0) g_c2[w] = p;
}

// ---------------------------------------------------------------------------
// Codebooks -> fp16 fragment chunks (identical layout to round-8, validated).
// ---------------------------------------------------------------------------
__global__ void cvt_cb_kernel(const float* __restrict__ cb) {
    int idx = blockIdx.x * 256 + threadIdx.x;
    if (idx >= Sx * Kx * 16) return;
    int tp = idx & 1;
    int kc = (idx >> 1) & 7;
    int gk = idx >> 4;                           // s*Kx + n
    const float* row = cb + (size_t)gk * Dx + kc * 16 + 4 * tp;
    uint4 v;
    v.x = pack_f16(row[0], row[1]);
    v.y = pack_f16(row[8], row[9]);
    v.z = pack_f16(row[2], row[3]);
    v.w = pack_f16(row[10], row[11]);
    int s = gk >> 10, n = gk & 1023;
    size_t dst = ((size_t)(s * 8 + (n >> 7)) * 128 + (n & 127)) * 16 + kc * 2 + tp;
    g_cbB[dst] = v;
}

// ---------------------------------------------------------------------------
// Fused 8-stage RVQ: 2-pass fp16 A-split mma + packed-key top-2 + rescore.
// grid = 256 CTAs x 256 threads; warp w owns rows w*16..w*16+15.
// ---------------------------------------------------------------------------
__global__ void __launch_bounds__(256, 1)
rvq_kernel(const float* __restrict__ x, const float* __restrict__ cb,
           float* __restrict__ out) {
    extern __shared__ char sm[];
    float*    R_sm = (float*)(sm + SMB_R);
    float*    c2s  = (float*)(sm + SMB_C2);
    uint32_t* k1s  = (uint32_t*)(sm + SMB_K1);
    uint32_t* k2s  = (uint32_t*)(sm + SMB_K2);
    int*      sidx = (int*)(sm + SMB_IDX);
    float*    red  = (float*)(sm + SMB_RED);
    const uint32_t smb = smem_u32(sm);

    const int tid  = threadIdx.x;
    const int wid  = tid >> 5;
    const int lane = tid & 31;
    const int g    = lane >> 2;
    const int tig  = lane & 3;
    const int wrow = wid * 16;
    const int row0 = blockIdx.x * 128;
    const int b    = row0 >> 12;
    const int t0   = row0 & (Tx - 1);
    const size_t QOFF = (size_t)Bx * Dx * Tx;

    // ---- initial residual: R[t][d] = x[b][d][t0+t] (coalesced over t) ----
    #pragma unroll
    for (int it = 0; it < 64; it++) {
        int idx = it * 256 + tid;
        int d = idx >> 7, tl = idx & 127;
        R_sm[tl * 132 + d] = x[((size_t)b * Dx + d) * Tx + t0 + tl];
    }
    __syncthreads();

    #pragma unroll 1
    for (int s = 0; s < Sx; s++) {
        // stage c2 into SMEM
        for (int i = tid; i < Kx; i += 256) c2s[i] = g_c2[s * Kx + i];

        // ---- A fragments (hi + lo fp16) for this warp's 16 rows ----
        uint32_t ah[8][4], al[8][4];
        #pragma unroll
        for (int kc = 0; kc < 8; kc++) {
            const float* base = &R_sm[(wrow + g) * 132 + kc * 16 + 2 * tig];
            float2 p0 = *(const float2*)(base);
            float2 p1 = *(const float2*)(base + 8 * 132);
            float2 p2 = *(const float2*)(base + 8);
            float2 p3 = *(const float2*)(base + 8 * 132 + 8);
            float h0x = __half2float(__float2half_rn(p0.x));
            float h0y = __half2float(__float2half_rn(p0.y));
            float h1x = __half2float(__float2half_rn(p1.x));
            float h1y = __half2float(__float2half_rn(p1.y));
            float h2x = __half2float(__float2half_rn(p2.x));
            float h2y = __half2float(__float2half_rn(p2.y));
            float h3x = __half2float(__float2half_rn(p3.x));
            float h3y = __half2float(__float2half_rn(p3.y));
            ah[kc][0] = pack_f16(h0x, h0y);
            ah[kc][1] = pack_f16(h1x, h1y);
            ah[kc][2] = pack_f16(h2x, h2y);
            ah[kc][3] = pack_f16(h3x, h3y);
            al[kc][0] = pack_f16(p0.x - h0x, p0.y - h0y);
            al[kc][1] = pack_f16(p1.x - h1x, p1.y - h1y);
            al[kc][2] = pack_f16(p2.x - h2x, p2.y - h2y);
            al[kc][3] = pack_f16(p3.x - h3x, p3.y - h3y);
        }

        // per-thread packed-key top-2 for two row-slots
        uint32_t ka1 = 0xFFFFFFFFu, ka2 = 0xFFFFFFFFu;
        uint32_t kb1 = 0xFFFFFFFFu, kb2 = 0xFFFFFFFFu;

        // ---- prefetch B tile nt=0 into buf 0 ----
        {
            const char* src = (const char*)(g_cbB + (size_t)(s * 8 + 0) * 2048);
            #pragma unroll
            for (int it = 0; it < 8; it++) {
                int idx = it * 256 + tid;
                int r = idx >> 4, c = idx & 15;
                CP_ASYNC16(smb + SMB_B + r * BROW + c * 16, src + r * 256 + c * 16);
            }
            CP_COMMIT();
        }

        #pragma unroll 1
        for (int nt = 0; nt < 8; nt++) {
            CP_WAIT0();
            __syncthreads();                 // B tile(nt) visible to all warps
            if (nt < 7) {                    // prefetch nt+1 into other buffer
                const char* src = (const char*)(g_cbB + (size_t)(s * 8 + nt + 1) * 2048);
                uint32_t dst = smb + SMB_B + ((nt + 1) & 1) * BBUF;
                #pragma unroll
                for (int it = 0; it < 8; it++) {
                    int idx = it * 256 + tid;
                    int r = idx >> 4, c = idx & 15;
                    CP_ASYNC16(dst + r * BROW + c * 16, src + r * 256 + c * 16);
                }
                CP_COMMIT();
            }

            const char* bbase = sm + SMB_B + (nt & 1) * BBUF;
            float acc[64];
            #pragma unroll
            for (int i = 0; i < 64; i++) acc[i] = 0.0f;

            // pass-outer ordering: same-acc MMAs are 16 apart (no dep stalls)
            #pragma unroll
            for (int pass = 0; pass < 2; pass++) {
                #pragma unroll
                for (int kc = 0; kc < 8; kc++) {
                    const uint32_t* afrag = pass ? al[kc] : ah[kc];
                    #pragma unroll
                    for (int nb = 0; nb < 16; nb++) {
                        uint2 bv = *(const uint2*)(bbase + (nb * 8 + g) * BROW
                                                   + kc * 32 + tig * 8);
                        mma_f16(&acc[nb * 4], afrag, bv.x, bv.y);
                    }
                }
            }

            // ---- fold distances into packed-key top-2 (branchless) ----
            #pragma unroll
            for (int nb = 0; nb < 16; nb++) {
                int n0 = nt * 128 + nb * 8 + 2 * tig;
                float2 cc = *(const float2*)&c2s[n0];
                float d0 = fmaf(-2.0f, acc[nb * 4 + 0], cc.x);
                float d1 = fmaf(-2.0f, acc[nb * 4 + 1], cc.y);
                float d2 = fmaf(-2.0f, acc[nb * 4 + 2], cc.x);
                float d3 = fmaf(-2.0f, acc[nb * 4 + 3], cc.y);
                ins2(ka1, ka2, mk_key(d0, n0));
                ins2(ka1, ka2, mk_key(d1, n0 + 1));
                ins2(kb1, kb2, mk_key(d2, n0));
                ins2(kb1, kb2, mk_key(d3, n0 + 1));
            }
        }

        // ---- merge top-2 across the 4 tig lanes ----
        #pragma unroll
        for (int off = 1; off <= 2; off <<= 1) {
            uint32_t o1 = __shfl_xor_sync(0xFFFFFFFFu, ka1, off);
            uint32_t o2 = __shfl_xor_sync(0xFFFFFFFFu, ka2, off);
            uint32_t mx = ka1 > o1 ? ka1 : o1;
            uint32_t mn2 = ka2 < o2 ? ka2 : o2;
            ka1 = ka1 < o1 ? ka1 : o1;
            ka2 = mx < mn2 ? mx : mn2;
            o1 = __shfl_xor_sync(0xFFFFFFFFu, kb1, off);
            o2 = __shfl_xor_sync(0xFFFFFFFFu, kb2, off);
            mx = kb1 > o1 ? kb1 : o1;
            mn2 = kb2 < o2 ? kb2 : o2;
            kb1 = kb1 < o1 ? kb1 : o1;
            kb2 = mx < mn2 ? mx : mn2;
        }
        if (tig == 0) {
            k1s[wrow + g] = ka1;     k2s[wrow + g] = ka2;
            k1s[wrow + g + 8] = kb1; k2s[wrow + g + 8] = kb2;
        }
        __syncthreads();

        // ---- pick: exact fp32 rescore when approx gap < TAU ----
        if (tid < 128) {
            uint32_t k1 = k1s[tid], k2 = k2s[tid];
            int i1 = (int)(k1 & 1023), i2 = (int)(k2 & 1023);
            int bi = i1;
            if (key_to_f(k2) - key_to_f(k1) < TAU) {
                const float4* rr4 = (const float4*)&R_sm[tid * 132];
                const float4* c1p = (const float4*)(cb + ((size_t)s * Kx + i1) * Dx);
                const float4* c2p = (const float4*)(cb + ((size_t)s * Kx + i2) * Dx);
                float s10 = 0.f, s11 = 0.f, s20 = 0.f, s21 = 0.f;
                #pragma unroll
                for (int j = 0; j < 32; j += 2) {
                    float4 a0 = rr4[j], a1 = rr4[j + 1];
                    float4 u0 = c1p[j], u1 = c1p[j + 1];
                    float4 w0 = c2p[j], w1 = c2p[j + 1];
                    s10 = fmaf(a0.x, u0.x, s10); s11 = fmaf(a0.y, u0.y, s11);
                    s10 = fmaf(a0.z, u0.z, s10); s11 = fmaf(a0.w, u0.w, s11);
                    s10 = fmaf(a1.x, u1.x, s10); s11 = fmaf(a1.y, u1.y, s11);
                    s10 = fmaf(a1.z, u1.z, s10); s11 = fmaf(a1.w, u1.w, s11);
                    s20 = fmaf(a0.x, w0.x, s20); s21 = fmaf(a0.y, w0.y, s21);
                    s20 = fmaf(a0.z, w0.z, s20); s21 = fmaf(a0.w, w0.w, s21);
                    s20 = fmaf(a1.x, w1.x, s20); s21 = fmaf(a1.y, w1.y, s21);
                    s20 = fmaf(a1.z, w1.z, s20); s21 = fmaf(a1.w, w1.w, s21);
                }
                float d1 = fmaf(-2.0f, s10 + s11, c2s[i1]);
                float d2 = fmaf(-2.0f, s20 + s21, c2s[i2]);
                if (d2 < d1 || (d2 == d1 && i2 < i1)) bi = i2;
            }
            sidx[tid] = bi;
            out[QOFF + (size_t)s * ROWS + row0 + tid] = (float)bi;
        }
        __syncthreads();

        // ---- residual update + commit partial ----
        float cm = 0.0f;
        #pragma unroll
        for (int it = 0; it < 64; it++) {
            int idx = it * 256 + tid;
            int m = idx >> 7, d = idx & 127;
            int k = sidx[m];
            float q  = cb[((size_t)s * Kx + k) * Dx + d];
            float r  = R_sm[m * 132 + d];
            float nr = r - q;
            cm = fmaf(nr, nr, cm);
            R_sm[m * 132 + d] = nr;
        }
        red[tid] = cm;
        __syncthreads();
        #pragma unroll
        for (int st = 128; st > 0; st >>= 1) {
            if (tid < st) red[tid] += red[tid + st];
            __syncthreads();
        }
        if (tid == 0) g_part[s * NCTAS + blockIdx.x] = red[0];
        __syncthreads();
    }

    // ---- quantized output: out[b][d][t] = x - R_final ----
    #pragma unroll
    for (int it = 0; it < 64; it++) {
        int idx = it * 256 + tid;
        int d = idx >> 7, tl = idx & 127;
        size_t go = ((size_t)b * Dx + d) * Tx + t0 + tl;
        out[go] = x[go] - R_sm[tl * 132 + d];
    }
}

// ---------------------------------------------------------------------------
// bw + penalty
// ---------------------------------------------------------------------------
__global__ void pack_kernel(float* __restrict__ out) {
    __shared__ float red[256];
    const size_t COFF = (size_t)Bx * Dx * Tx + (size_t)Sx * ROWS;
    int tid = threadIdx.x;
    float s = 0.0f;
    for (int i = tid; i < Sx * NCTAS; i += 256) s += g_part[i];
    red[tid] = s;
    __syncthreads();
    #pragma unroll
    for (int st = 128; st > 0; st >>= 1) {
        if (tid < st) red[tid] += red[tid + st];
        __syncthreads();
    }
    if (tid == 0) {
        out[COFF + 0] = 6000.0f;   // 8 * log2(1024) * 75
        out[COFF + 1] = red[0] / ((float)Sx * (float)ROWS * (float)Dx);
    }
}

extern "C" void kernel_launch(void* const* d_in, const int* in_sizes, int n_in,
                              void* d_out, int out_size) {
    const float* x  = (const float*)d_in[0];
    const float* cb = (const float*)d_in[1];
    float* out = (float*)d_out;

    cudaFuncSetAttribute(rvq_kernel, cudaFuncAttributeMaxDynamicSharedMemorySize,
                         SMEM_TOTAL);

    c2_kernel<<<(Sx * Kx * 32) / 256, 256>>>(cb);
    cvt_cb_kernel<<<(Sx * Kx * 16) / 256, 256>>>(cb);
    rvq_kernel<<<NCTAS, 256, SMEM_TOTAL>>>(x, cb, out);
    pack_kernel<<<1, 256>>>(out);
}

// round 10
// speedup vs baseline: 3.3685x; 1.4118x over previous
#include <cuda_runtime.h>
#include <cuda_fp16.h>
#include <cstdint>

#define Bx 8
#define Dx 128
#define Tx 4096
#define Kx 1024
#define Sx 8
#define ROWS (Bx*Tx)            // 32768
#define NCTAS (ROWS/128)        // 256
#define TAU 0.35f               // rescore window (>> 4-sigma err + key quant)
#define KEYMASK 0xFFFFFC00u

// ---------------- device scratch (no runtime allocation) -------------------
__device__ float g_c2[Sx * Kx];                 // ||c||^2 fp32
__device__ float g_part[Sx * NCTAS];            // commit partials
// fp16 B fragment bundles: per (s,nt) tile: 128 rows x 256B (validated layout)
__device__ uint4 g_cbB[(size_t)Sx * Kx * 16];   // 2 MB

// ---------------- SMEM layout (byte offsets) --------------------------------
#define BROW    288           // padded B row stride (conflict-free LDS.64)
#define BBUF_H  18432         // 64 rows * 288  (half-tile buffer)
#define SMB_B   0             // 2 x BBUF_H = 36864
#define SMB_R   36864         // 128 x 132 fp32 = 67584
#define SMB_C2  104448        // 1024 fp32 = 4096
#define SMB_K1  108544        // 128 u32
#define SMB_K2  109056        // 128 u32
#define SMB_K3  109568        // 128 u32
#define SMB_IDX 110080        // 128 int
#define SMB_RED 110592        // 256 fp32
#define SMEM_TOTAL 111616     // fits 2 CTAs/SM (223232 <= 228KB)

// ---------------- helpers ----------------------------------------------------
__device__ __forceinline__ uint32_t pack_f16(float a, float b) {
    __half2 h = __floats2half2_rn(a, b);
    return *reinterpret_cast<uint32_t*>(&h);
}
__device__ __forceinline__ uint32_t smem_u32(const void* p) {
    uint32_t a;
    asm("{ .reg .u64 t; cvta.to.shared.u64 t, %1; cvt.u32.u64 %0, t; }" : "=r"(a) : "l"(p));
    return a;
}

// m16n8k16 row.col fp16 MMA, fp32 accumulate (in place)
__device__ __forceinline__ void mma_f16(float* c, const uint32_t* a,
                                        uint32_t b0, uint32_t b1) {
    asm volatile(
        "mma.sync.aligned.m16n8k16.row.col.f32.f16.f16.f32 "
        "{%0,%1,%2,%3}, {%4,%5,%6,%7}, {%8,%9}, {%0,%1,%2,%3};"
        : "+f"(c[0]), "+f"(c[1]), "+f"(c[2]), "+f"(c[3])
        : "r"(a[0]), "r"(a[1]), "r"(a[2]), "r"(a[3]), "r"(b0), "r"(b1));
}

#define CP_ASYNC16(dst, src) \
    asm volatile("cp.async.cg.shared.global [%0], [%1], 16;" :: "r"(dst), "l"(src))
#define CP_COMMIT() asm volatile("cp.async.commit_group;" ::: "memory")
#define CP_WAIT0()  asm volatile("cp.async.wait_group 0;" ::: "memory")

// order-preserving float->uint, low 10 bits replaced by candidate index
__device__ __forceinline__ uint32_t mk_key(float d, int n) {
    uint32_t b = __float_as_uint(d);
    uint32_t u = b ^ ((uint32_t)((int32_t)b >> 31) | 0x80000000u);
    return (u & KEYMASK) | (uint32_t)n;
}
// approximate inverse (low bits zeroed)
__device__ __forceinline__ float key_to_f(uint32_t k) {
    uint32_t u = k & KEYMASK;
    uint32_t b = (u & 0x80000000u) ? (u ^ 0x80000000u) : ~u;
    return __uint_as_float(b);
}
// branchless sorted top-3 insert (ascending keys; index in low bits =>
// smaller index wins ties automatically)
__device__ __forceinline__ void ins3(uint32_t& v1, uint32_t& v2, uint32_t& v3,
                                     uint32_t k) {
    uint32_t c  = v3 < k ? v3 : k;        // drop max(v3, k)
    uint32_t lo = v2 < c ? v2 : c;
    uint32_t hi = v2 < c ? c : v2;
    v3 = hi;
    uint32_t n1 = v1 < lo ? v1 : lo;
    v2 = v1 < lo ? lo : v1;
    v1 = n1;
}

// ---------------------------------------------------------------------------
// ||c||^2 for all stages: one warp per codeword.
// ---------------------------------------------------------------------------
__global__ void c2_kernel(const float* __restrict__ cb) {
    int w    = (blockIdx.x * blockDim.x + threadIdx.x) >> 5;
    int lane = threadIdx.x & 31;
    if (w >= Sx * Kx) return;
    float4 v = reinterpret_cast<const float4*>(cb)[(size_t)w * 32 + lane];
    float p = v.x * v.x + v.y * v.y + v.z * v.z + v.w * v.w;
    #pragma unroll
    for (int o = 16; o; o >>= 1) p += __shfl_down_sync(0xFFFFFFFFu, p, o);
    if (lane == 0) g_c2[w] = p;
}

// ---------------------------------------------------------------------------
// Codebooks -> fp16 fragment chunks (layout validated rounds 8-9).
// ---------------------------------------------------------------------------
__global__ void cvt_cb_kernel(const float* __restrict__ cb) {
    int idx = blockIdx.x * 256 + threadIdx.x;
    if (idx >= Sx * Kx * 16) return;
    int tp = idx & 1;
    int kc = (idx >> 1) & 7;
    int gk = idx >> 4;                           // s*Kx + n
    const float* row = cb + (size_t)gk * Dx + kc * 16 + 4 * tp;
    uint4 v;
    v.x = pack_f16(row[0], row[1]);
    v.y = pack_f16(row[8], row[9]);
    v.z = pack_f16(row[2], row[3]);
    v.w = pack_f16(row[10], row[11]);
    int s = gk >> 10, n = gk & 1023;
    size_t dst = ((size_t)(s * 8 + (n >> 7)) * 128 + (n & 127)) * 16 + kc * 2 + tp;
    g_cbB[dst] = v;
}

// ---------------------------------------------------------------------------
// Fused 8-stage RVQ: 1-pass fp16 mma + packed-key top-3 + exact rescore.
// grid = 256 CTAs x 256 threads, 2 CTAs/SM; warp w owns rows w*16..w*16+15.
// ---------------------------------------------------------------------------
__global__ void __launch_bounds__(256, 2)
rvq_kernel(const float* __restrict__ x, const float* __restrict__ cb,
           float* __restrict__ out) {
    extern __shared__ char sm[];
    float*    R_sm = (float*)(sm + SMB_R);
    float*    c2s  = (float*)(sm + SMB_C2);
    uint32_t* k1s  = (uint32_t*)(sm + SMB_K1);
    uint32_t* k2s  = (uint32_t*)(sm + SMB_K2);
    uint32_t* k3s  = (uint32_t*)(sm + SMB_K3);
    int*      sidx = (int*)(sm + SMB_IDX);
    float*    red  = (float*)(sm + SMB_RED);
    const uint32_t smb = smem_u32(sm);

    const int tid  = threadIdx.x;
    const int lane = tid & 31;
    const int g    = lane >> 2;
    const int tig  = lane & 3;
    const int wrow = (tid >> 5) * 16;
    const int row0 = blockIdx.x * 128;
    const int b    = row0 >> 12;
    const int t0   = row0 & (Tx - 1);
    const size_t QOFF = (size_t)Bx * Dx * Tx;

    // ---- initial residual: R[t][d] = x[b][d][t0+t] (coalesced over t) ----
    #pragma unroll
    for (int it = 0; it < 64; it++) {
        int idx = it * 256 + tid;
        int d = idx >> 7, tl = idx & 127;
        R_sm[tl * 132 + d] = x[((size_t)b * Dx + d) * Tx + t0 + tl];
    }
    __syncthreads();

    #pragma unroll 1
    for (int s = 0; s < Sx; s++) {
        // ---- prefetch B half-tile 0 of this stage ----
        {
            const char* src = (const char*)(g_cbB + (size_t)(s * 8) * 2048);
            #pragma unroll
            for (int it = 0; it < 4; it++) {
                int idx = it * 256 + tid;
                int r = idx >> 4, c = idx & 15;
                CP_ASYNC16(smb + SMB_B + r * BROW + c * 16, src + r * 256 + c * 16);
            }
            CP_COMMIT();
        }

        // stage c2 into SMEM
        for (int i = tid; i < Kx; i += 256) c2s[i] = g_c2[s * Kx + i];

        // ---- A fragments (fp16) for this warp's 16 rows, reused all tiles ----
        uint32_t ah[8][4];
        #pragma unroll
        for (int kc = 0; kc < 8; kc++) {
            const float* base = &R_sm[(wrow + g) * 132 + kc * 16 + 2 * tig];
            float2 p0 = *(const float2*)(base);
            float2 p1 = *(const float2*)(base + 8 * 132);
            float2 p2 = *(const float2*)(base + 8);
            float2 p3 = *(const float2*)(base + 8 * 132 + 8);
            ah[kc][0] = pack_f16(p0.x, p0.y);
            ah[kc][1] = pack_f16(p1.x, p1.y);
            ah[kc][2] = pack_f16(p2.x, p2.y);
            ah[kc][3] = pack_f16(p3.x, p3.y);
        }

        // per-thread packed-key top-3 for two row-slots
        uint32_t ka1 = 0xFFFFFFFFu, ka2 = 0xFFFFFFFFu, ka3 = 0xFFFFFFFFu;
        uint32_t kb1 = 0xFFFFFFFFu, kb2 = 0xFFFFFFFFu, kb3 = 0xFFFFFFFFu;

        // ---- 16 half-tiles of 64 codewords, ping-pong buffered ----
        #pragma unroll 1
        for (int h = 0; h < 16; h++) {
            CP_WAIT0();
            __syncthreads();                 // half(h) visible; other buf free
            if (h < 15) {                    // prefetch h+1 into other buffer
                const char* src = (const char*)(g_cbB + (size_t)(s * 8) * 2048)
                                + (h + 1) * 16384;
                uint32_t dst = smb + SMB_B + ((h + 1) & 1) * BBUF_H;
                #pragma unroll
                for (int it = 0; it < 4; it++) {
                    int idx = it * 256 + tid;
                    int r = idx >> 4, c = idx & 15;
                    CP_ASYNC16(dst + r * BROW + c * 16, src + r * 256 + c * 16);
                }
                CP_COMMIT();
            }

            const char* bbase = sm + SMB_B + (h & 1) * BBUF_H;
            float acc[32];
            #pragma unroll
            for (int i = 0; i < 32; i++) acc[i] = 0.0f;

            #pragma unroll
            for (int kc = 0; kc < 8; kc++) {
                #pragma unroll
                for (int nb = 0; nb < 8; nb++) {
                    uint2 bv = *(const uint2*)(bbase + (nb * 8 + g) * BROW
                                               + kc * 32 + tig * 8);
                    mma_f16(&acc[nb * 4], ah[kc], bv.x, bv.y);
                }
            }

            // ---- fold distances into packed-key top-3 (branchless) ----
            #pragma unroll
            for (int nb = 0; nb < 8; nb++) {
                int n0 = h * 64 + nb * 8 + 2 * tig;
                float2 cc = *(const float2*)&c2s[n0];
                float d0 = fmaf(-2.0f, acc[nb * 4 + 0], cc.x);
                float d1 = fmaf(-2.0f, acc[nb * 4 + 1], cc.y);
                float d2 = fmaf(-2.0f, acc[nb * 4 + 2], cc.x);
                float d3 = fmaf(-2.0f, acc[nb * 4 + 3], cc.y);
                ins3(ka1, ka2, ka3, mk_key(d0, n0));
                ins3(ka1, ka2, ka3, mk_key(d1, n0 + 1));
                ins3(kb1, kb2, kb3, mk_key(d2, n0));
                ins3(kb1, kb2, kb3, mk_key(d3, n0 + 1));
            }
        }

        // ---- merge top-3 across the 4 tig lanes ----
        #pragma unroll
        for (int off = 1; off <= 2; off <<= 1) {
            uint32_t o1 = __shfl_xor_sync(0xFFFFFFFFu, ka1, off);
            uint32_t o2 = __shfl_xor_sync(0xFFFFFFFFu, ka2, off);
            uint32_t o3 = __shfl_xor_sync(0xFFFFFFFFu, ka3, off);
            ins3(ka1, ka2, ka3, o1);
            ins3(ka1, ka2, ka3, o2);
            ins3(ka1, ka2, ka3, o3);
            o1 = __shfl_xor_sync(0xFFFFFFFFu, kb1, off);
            o2 = __shfl_xor_sync(0xFFFFFFFFu, kb2, off);
            o3 = __shfl_xor_sync(0xFFFFFFFFu, kb3, off);
            ins3(kb1, kb2, kb3, o1);
            ins3(kb1, kb2, kb3, o2);
            ins3(kb1, kb2, kb3, o3);
        }
        if (tig == 0) {
            k1s[wrow + g] = ka1; k2s[wrow + g] = ka2; k3s[wrow + g] = ka3;
            k1s[wrow + g + 8] = kb1; k2s[wrow + g + 8] = kb2; k3s[wrow + g + 8] = kb3;
        }
        __syncthreads();

        // ---- pick: exact fp32 rescore of all candidates within TAU ----
        if (tid < 128) {
            uint32_t k1 = k1s[tid], k2 = k2s[tid], k3 = k3s[tid];
            int bi = (int)(k1 & 1023);
            float f1 = key_to_f(k1);
            if (key_to_f(k2) - f1 < TAU) {
                int ncand = (key_to_f(k3) - f1 < TAU) ? 3 : 2;
                int cand[3] = {(int)(k1 & 1023), (int)(k2 & 1023), (int)(k3 & 1023)};
                const float4* rr4 = (const float4*)&R_sm[tid * 132];
                float bestd = __int_as_float(0x7F800000);
                int   besti = 0x7fffffff;
                #pragma unroll 1
                for (int j = 0; j < ncand; j++) {
                    int k = cand[j];
                    const float4* cp4 = (const float4*)(cb + ((size_t)s * Kx + k) * Dx);
                    float s0 = 0.f, s1 = 0.f, s2 = 0.f, s3 = 0.f;
                    #pragma unroll
                    for (int q = 0; q < 32; q += 4) {
                        float4 a0 = rr4[q],     u0 = cp4[q];
                        float4 a1 = rr4[q + 1], u1 = cp4[q + 1];
                        float4 a2 = rr4[q + 2], u2 = cp4[q + 2];
                        float4 a3 = rr4[q + 3], u3 = cp4[q + 3];
                        s0 = fmaf(a0.x, u0.x, s0); s1 = fmaf(a0.y, u0.y, s1);
                        s2 = fmaf(a0.z, u0.z, s2); s3 = fmaf(a0.w, u0.w, s3);
                        s0 = fmaf(a1.x, u1.x, s0); s1 = fmaf(a1.y, u1.y, s1);
                        s2 = fmaf(a1.z, u1.z, s2); s3 = fmaf(a1.w, u1.w, s3);
                        s0 = fmaf(a2.x, u2.x, s0); s1 = fmaf(a2.y, u2.y, s1);
                        s2 = fmaf(a2.z, u2.z, s2); s3 = fmaf(a2.w, u2.w, s3);
                        s0 = fmaf(a3.x, u3.x, s0); s1 = fmaf(a3.y, u3.y, s1);
                        s2 = fmaf(a3.z, u3.z, s2); s3 = fmaf(a3.w, u3.w, s3);
                    }
                    float dex = fmaf(-2.0f, (s0 + s1) + (s2 + s3), c2s[k]);
                    if (dex < bestd || (dex == bestd && k < besti)) {
                        bestd = dex; besti = k;
                    }
                }
                bi = besti;
            }
            sidx[tid] = bi;
            out[QOFF + (size_t)s * ROWS + row0 + tid] = (float)bi;
        }
        __syncthreads();

        // ---- residual update + commit partial ----
        float cm = 0.0f;
        #pragma unroll
        for (int it = 0; it < 64; it++) {
            int idx = it * 256 + tid;
            int m = idx >> 7, d = idx & 127;
            int k = sidx[m];
            float q  = cb[((size_t)s * Kx + k) * Dx + d];
            float r  = R_sm[m * 132 + d];
            float nr = r - q;
            cm = fmaf(nr, nr, cm);
            R_sm[m * 132 + d] = nr;
        }
        red[tid] = cm;
        __syncthreads();
        #pragma unroll
        for (int st = 128; st > 0; st >>= 1) {
            if (tid < st) red[tid] += red[tid + st];
            __syncthreads();
        }
        if (tid == 0) g_part[s * NCTAS + blockIdx.x] = red[0];
        __syncthreads();
    }

    // ---- quantized output: out[b][d][t] = x - R_final ----
    #pragma unroll
    for (int it = 0; it < 64; it++) {
        int idx = it * 256 + tid;
        int d = idx >> 7, tl = idx & 127;
        size_t go = ((size_t)b * Dx + d) * Tx + t0 + tl;
        out[go] = x[go] - R_sm[tl * 132 + d];
    }
}

// ---------------------------------------------------------------------------
// bw + penalty
// ---------------------------------------------------------------------------
__global__ void pack_kernel(float* __restrict__ out) {
    __shared__ float red[256];
    const size_t COFF = (size_t)Bx * Dx * Tx + (size_t)Sx * ROWS;
    int tid = threadIdx.x;
    float s = 0.0f;
    for (int i = tid; i < Sx * NCTAS; i += 256) s += g_part[i];
    red[tid] = s;
    __syncthreads();
    #pragma unroll
    for (int st = 128; st > 0; st >>= 1) {
        if (tid < st) red[tid] += red[tid + st];
        __syncthreads();
    }
    if (tid == 0) {
        out[COFF + 0] = 6000.0f;   // 8 * log2(1024) * 75
        out[COFF + 1] = red[0] / ((float)Sx * (float)ROWS * (float)Dx);
    }
}

extern "C" void kernel_launch(void* const* d_in, const int* in_sizes, int n_in,
                              void* d_out, int out_size) {
    const float* x  = (const float*)d_in[0];
    const float* cb = (const float*)d_in[1];
    float* out = (float*)d_out;

    cudaFuncSetAttribute(rvq_kernel, cudaFuncAttributeMaxDynamicSharedMemorySize,
                         SMEM_TOTAL);

    c2_kernel<<<(Sx * Kx * 32) / 256, 256>>>(cb);
    cvt_cb_kernel<<<(Sx * Kx * 16) / 256, 256>>>(cb);
    rvq_kernel<<<NCTAS, 256, SMEM_TOTAL>>>(x, cb, out);
    pack_kernel<<<1, 256>>>(out);
}

// round 12
// speedup vs baseline: 3.6591x; 1.0862x over previous
#include <cuda_runtime.h>
#include <cuda_fp16.h>
#include <cstdint>

#define Bx 8
#define Dx 128
#define Tx 4096
#define Kx 1024
#define Sx 8
#define ROWS (Bx*Tx)            // 32768
#define NCTAS (ROWS/128)        // 256
#define TAU 0.60f               // rescore window (4-sigma err + 2x key quant)
#define KEYMASK 0xFFFFFC00u
#define C2BIAS 512.0f           // makes folded distances strictly positive

// ---------------- device scratch (no runtime allocation) -------------------
__device__ float g_c2[Sx * Kx];                 // ||c||^2 fp32
__device__ float g_part[Sx * NCTAS];            // commit partials
// fp16 B fragment bundles: per (s,nt) tile: 128 rows x 256B (validated layout)
__device__ uint4 g_cbB[(size_t)Sx * Kx * 16];   // 2 MB

// ---------------- SMEM layout (byte offsets) --------------------------------
#define BROW    288           // padded B row stride (conflict-free LDS.64)
#define BBUF_H  18432         // 64 rows * 288  (half-tile buffer)
#define SMB_B   0             // 2 x BBUF_H = 36864
#define SMB_R   36864         // 128 x 132 fp32 = 67584
#define SMB_C2  104448        // 1024 fp32 = 4096  (BIASED by C2BIAS)
#define SMB_K1  108544        // 128 u32
#define SMB_K2  109056        // 128 u32
#define SMB_K3  109568        // 128 u32
#define SMB_IDX 110080        // 128 int
#define SMB_RED 110592        // 256 fp32
#define SMEM_TOTAL 111616     // fits 2 CTAs/SM

// ---------------- helpers ----------------------------------------------------
__device__ __forceinline__ uint32_t pack_f16(float a, float b) {
    __half2 h = __floats2half2_rn(a, b);
    return *reinterpret_cast<uint32_t*>(&h);
}
__device__ __forceinline__ uint32_t smem_u32(const void* p) {
    uint32_t a;
    asm("{ .reg .u64 t; cvta.to.shared.u64 t, %1; cvt.u32.u64 %0, t; }" : "=r"(a) : "l"(p));
    return a;
}

// m16n8k16 row.col fp16 MMA, fp32 accumulate (in place)
__device__ __forceinline__ void mma_f16(float* c, const uint32_t* a,
                                        uint32_t b0, uint32_t b1) {
    asm volatile(
        "mma.sync.aligned.m16n8k16.row.col.f32.f16.f16.f32 "
        "{%0,%1,%2,%3}, {%4,%5,%6,%7}, {%8,%9}, {%0,%1,%2,%3};"
        : "+f"(c[0]), "+f"(c[1]), "+f"(c[2]), "+f"(c[3])
        : "r"(a[0]), "r"(a[1]), "r"(a[2]), "r"(a[3]), "r"(b0), "r"(b1));
}

#define CP_ASYNC16(dst, src) \
    asm volatile("cp.async.cg.shared.global [%0], [%1], 16;" :: "r"(dst), "l"(src))
#define CP_COMMIT() asm volatile("cp.async.commit_group;" ::: "memory")
#define CP_WAIT0()  asm volatile("cp.async.wait_group 0;" ::: "memory")

// key for strictly-POSITIVE biased distances: raw float bits are order-
// preserving; low 10 mantissa bits carry the candidate index (smaller idx
// wins ties automatically). One LOP3.
__device__ __forceinline__ uint32_t mk_key(float d, int n) {
    return (__float_as_uint(d) & KEYMASK) | (uint32_t)n;
}
__device__ __forceinline__ float key_to_f(uint32_t k) {
    return __uint_as_float(k & KEYMASK);   // biased value; bias cancels in gaps
}
// branchless sorted top-3 insert (ascending keys)
__device__ __forceinline__ void ins3(uint32_t& v1, uint32_t& v2, uint32_t& v3,
                                     uint32_t k) {
    uint32_t c  = v3 < k ? v3 : k;        // drop max(v3, k)
    uint32_t lo = v2 < c ? v2 : c;
    uint32_t hi = v2 < c ? c : v2;
    v3 = hi;
    uint32_t n1 = v1 < lo ? v1 : lo;
    v2 = v1 < lo ? lo : v1;
    v1 = n1;
}

// ---------------------------------------------------------------------------
// ||c||^2 for all stages: one warp per codeword.
// ---------------------------------------------------------------------------
__global__ void c2_kernel(const float* __restrict__ cb) {
    int w    = (blockIdx.x * blockDim.x + threadIdx.x) >> 5;
    int lane = threadIdx.x & 31;
    if (w >= Sx * Kx) return;
    float4 v = reinterpret_cast<const float4*>(cb)[(size_t)w * 32 + lane];
    float p = v.x * v.x + v.y * v.y + v.z * v.z + v.w * v.w;
    #pragma unroll
    for (int o = 16; o; o >>= 1) p += __shfl_down_sync(0xFFFFFFFFu, p, o);
    if (lane == 0) g_c2[w] = p;
}

// ---------------------------------------------------------------------------
// Codebooks -> fp16 fragment chunks (layout validated rounds 8-10).
// ---------------------------------------------------------------------------
__global__ void cvt_cb_kernel(const float* __restrict__ cb) {
    int idx = blockIdx.x * 256 + threadIdx.x;
    if (idx >= Sx * Kx * 16) return;
    int tp = idx & 1;
    int kc = (idx >> 1) & 7;
    int gk = idx >> 4;                           // s*Kx + n
    const float* row = cb + (size_t)gk * Dx + kc * 16 + 4 * tp;
    uint4 v;
    v.x = pack_f16(row[0], row[1]);
    v.y = pack_f16(row[8], row[9]);
    v.z = pack_f16(row[2], row[3]);
    v.w = pack_f16(row[10], row[11]);
    int s = gk >> 10, n = gk & 1023;
    size_t dst = ((size_t)(s * 8 + (n >> 7)) * 128 + (n & 127)) * 16 + kc * 2 + tp;
    g_cbB[dst] = v;
}

// ---------------------------------------------------------------------------
// Fused 8-stage RVQ: 1-pass fp16 mma + biased-key top-3 + exact rescore.
// grid = 256 CTAs x 256 threads, 2 CTAs/SM; warp w owns rows w*16..w*16+15.
// ---------------------------------------------------------------------------
__global__ void __launch_bounds__(256, 2)
rvq_kernel(const float* __restrict__ x, const float* __restrict__ cb,
           float* __restrict__ out) {
    extern __shared__ char sm[];
    float*    R_sm = (float*)(sm + SMB_R);
    float*    c2s  = (float*)(sm + SMB_C2);
    uint32_t* k1s  = (uint32_t*)(sm + SMB_K1);
    uint32_t* k2s  = (uint32_t*)(sm + SMB_K2);
    uint32_t* k3s  = (uint32_t*)(sm + SMB_K3);
    int*      sidx = (int*)(sm + SMB_IDX);
    float*    red  = (float*)(sm + SMB_RED);
    const uint32_t smb = smem_u32(sm);

    const int tid  = threadIdx.x;
    const int lane = tid & 31;
    const int g    = lane >> 2;
    const int tig  = lane & 3;
    const int wrow = (tid >> 5) * 16;
    const int row0 = blockIdx.x * 128;
    const int b    = row0 >> 12;
    const int t0   = row0 & (Tx - 1);
    const size_t QOFF = (size_t)Bx * Dx * Tx;

    // ---- initial residual: R[t][d] = x[b][d][t0+t] (coalesced over t) ----
    #pragma unroll
    for (int it = 0; it < 64; it++) {
        int idx = it * 256 + tid;
        int d = idx >> 7, tl = idx & 127;
        R_sm[tl * 132 + d] = x[((size_t)b * Dx + d) * Tx + t0 + tl];
    }
    __syncthreads();

    #pragma unroll 1
    for (int s = 0; s < Sx; s++) {
        // ---- prefetch B half-tile 0 of this stage ----
        {
            const char* src = (const char*)(g_cbB + (size_t)(s * 8) * 2048);
            #pragma unroll
            for (int it = 0; it < 4; it++) {
                int idx = it * 256 + tid;
                int r = idx >> 4, c = idx & 15;
                CP_ASYNC16(smb + SMB_B + r * BROW + c * 16, src + r * 256 + c * 16);
            }
            CP_COMMIT();
        }

        // stage BIASED c2 into SMEM (guarantees positive folded distances)
        for (int i = tid; i < Kx; i += 256) c2s[i] = g_c2[s * Kx + i] + C2BIAS;

        // ---- A fragments (fp16) for this warp's 16 rows, reused all tiles ----
        uint32_t ah[8][4];
        #pragma unroll
        for (int kc = 0; kc < 8; kc++) {
            const float* base = &R_sm[(wrow + g) * 132 + kc * 16 + 2 * tig];
            float2 p0 = *(const float2*)(base);
            float2 p1 = *(const float2*)(base + 8 * 132);
            float2 p2 = *(const float2*)(base + 8);
            float2 p3 = *(const float2*)(base + 8 * 132 + 8);
            ah[kc][0] = pack_f16(p0.x, p0.y);
            ah[kc][1] = pack_f16(p1.x, p1.y);
            ah[kc][2] = pack_f16(p2.x, p2.y);
            ah[kc][3] = pack_f16(p3.x, p3.y);
        }

        // per-thread packed-key top-3 for two row-slots
        uint32_t ka1 = 0xFFFFFFFFu, ka2 = 0xFFFFFFFFu, ka3 = 0xFFFFFFFFu;
        uint32_t kb1 = 0xFFFFFFFFu, kb2 = 0xFFFFFFFFu, kb3 = 0xFFFFFFFFu;

        // ---- 16 half-tiles of 64 codewords, ping-pong buffered ----
        #pragma unroll 1
        for (int h = 0; h < 16; h++) {
            CP_WAIT0();
            __syncthreads();                 // half(h) visible; other buf free
            if (h < 15) {                    // prefetch h+1 into other buffer
                const char* src = (const char*)(g_cbB + (size_t)(s * 8) * 2048)
                                + (h + 1) * 16384;
                uint32_t dst = smb + SMB_B + ((h + 1) & 1) * BBUF_H;
                #pragma unroll
                for (int it = 0; it < 4; it++) {
                    int idx = it * 256 + tid;
                    int r = idx >> 4, c = idx & 15;
                    CP_ASYNC16(dst + r * BROW + c * 16, src + r * 256 + c * 16);
                }
                CP_COMMIT();
            }

            const char* bbase = sm + SMB_B + (h & 1) * BBUF_H;
            float acc[32];
            #pragma unroll
            for (int i = 0; i < 32; i++) acc[i] = 0.0f;

            #pragma unroll
            for (int kc = 0; kc < 8; kc++) {
                #pragma unroll
                for (int nb = 0; nb < 8; nb++) {
                    uint2 bv = *(const uint2*)(bbase + (nb * 8 + g) * BROW
                                               + kc * 32 + tig * 8);
                    mma_f16(&acc[nb * 4], ah[kc], bv.x, bv.y);
                }
            }

            // ---- fold distances into packed-key top-3 (~7 ops/candidate) ----
            #pragma unroll
            for (int nb = 0; nb < 8; nb++) {
                int n0 = h * 64 + nb * 8 + 2 * tig;
                float2 cc = *(const float2*)&c2s[n0];
                float d0 = fmaf(-2.0f, acc[nb * 4 + 0], cc.x);
                float d1 = fmaf(-2.0f, acc[nb * 4 + 1], cc.y);
                float d2 = fmaf(-2.0f, acc[nb * 4 + 2], cc.x);
                float d3 = fmaf(-2.0f, acc[nb * 4 + 3], cc.y);
                ins3(ka1, ka2, ka3, mk_key(d0, n0));
                ins3(ka1, ka2, ka3, mk_key(d1, n0 + 1));
                ins3(kb1, kb2, kb3, mk_key(d2, n0));
                ins3(kb1, kb2, kb3, mk_key(d3, n0 + 1));
            }
        }

        // ---- merge top-3 across the 4 tig lanes ----
        #pragma unroll
        for (int off = 1; off <= 2; off <<= 1) {
            uint32_t o1 = __shfl_xor_sync(0xFFFFFFFFu, ka1, off);
            uint32_t o2 = __shfl_xor_sync(0xFFFFFFFFu, ka2, off);
            uint32_t o3 = __shfl_xor_sync(0xFFFFFFFFu, ka3, off);
            ins3(ka1, ka2, ka3, o1);
            ins3(ka1, ka2, ka3, o2);
            ins3(ka1, ka2, ka3, o3);
            o1 = __shfl_xor_sync(0xFFFFFFFFu, kb1, off);
            o2 = __shfl_xor_sync(0xFFFFFFFFu, kb2, off);
            o3 = __shfl_xor_sync(0xFFFFFFFFu, kb3, off);
            ins3(kb1, kb2, kb3, o1);
            ins3(kb1, kb2, kb3, o2);
            ins3(kb1, kb2, kb3, o3);
        }
        if (tig == 0) {
            k1s[wrow + g] = ka1; k2s[wrow + g] = ka2; k3s[wrow + g] = ka3;
            k1s[wrow + g + 8] = kb1; k2s[wrow + g + 8] = kb2; k3s[wrow + g + 8] = kb3;
        }
        __syncthreads();

        // ---- pick: exact fp32 rescore of all candidates within TAU ----
        if (tid < 128) {
            uint32_t k1 = k1s[tid], k2 = k2s[tid], k3 = k3s[tid];
            int bi = (int)(k1 & 1023);
            float f1 = key_to_f(k1);
            if (key_to_f(k2) - f1 < TAU) {
                int ncand = (key_to_f(k3) - f1 < TAU) ? 3 : 2;
                int cand[3] = {(int)(k1 & 1023), (int)(k2 & 1023), (int)(k3 & 1023)};
                const float4* rr4 = (const float4*)&R_sm[tid * 132];
                float bestd = __int_as_float(0x7F800000);
                int   besti = 0x7fffffff;
                #pragma unroll 1
                for (int j = 0; j < ncand; j++) {
                    int k = cand[j];
                    const float4* cp4 = (const float4*)(cb + ((size_t)s * Kx + k) * Dx);
                    float s0 = 0.f, s1 = 0.f, s2 = 0.f, s3 = 0.f;
                    #pragma unroll
                    for (int q = 0; q < 32; q += 4) {
                        float4 a0 = rr4[q],     u0 = cp4[q];
                        float4 a1 = rr4[q + 1], u1 = cp4[q + 1];
                        float4 a2 = rr4[q + 2], u2 = cp4[q + 2];
                        float4 a3 = rr4[q + 3], u3 = cp4[q + 3];
                        s0 = fmaf(a0.x, u0.x, s0); s1 = fmaf(a0.y, u0.y, s1);
                        s2 = fmaf(a0.z, u0.z, s2); s3 = fmaf(a0.w, u0.w, s3);
                        s0 = fmaf(a1.x, u1.x, s0); s1 = fmaf(a1.y, u1.y, s1);
                        s2 = fmaf(a1.z, u1.z, s2); s3 = fmaf(a1.w, u1.w, s3);
                        s0 = fmaf(a2.x, u2.x, s0); s1 = fmaf(a2.y, u2.y, s1);
                        s2 = fmaf(a2.z, u2.z, s2); s3 = fmaf(a2.w, u2.w, s3);
                        s0 = fmaf(a3.x, u3.x, s0); s1 = fmaf(a3.y, u3.y, s1);
                        s2 = fmaf(a3.z, u3.z, s2); s3 = fmaf(a3.w, u3.w, s3);
                    }
                    // biased distance: bias is constant, ordering unchanged
                    float dex = fmaf(-2.0f, (s0 + s1) + (s2 + s3), c2s[k]);
                    if (dex < bestd || (dex == bestd && k < besti)) {
                        bestd = dex; besti = k;
                    }
                }
                bi = besti;
            }
            sidx[tid] = bi;
            out[QOFF + (size_t)s * ROWS + row0 + tid] = (float)bi;
        }
        __syncthreads();

        // ---- residual update + commit partial ----
        float cm = 0.0f;
        #pragma unroll
        for (int it = 0; it < 64; it++) {
            int idx = it * 256 + tid;
            int m = idx >> 7, d = idx & 127;
            int k = sidx[m];
            float q  = cb[((size_t)s * Kx + k) * Dx + d];
            float r  = R_sm[m * 132 + d];
            float nr = r - q;
            cm = fmaf(nr, nr, cm);
            R_sm[m * 132 + d] = nr;
        }
        red[tid] = cm;
        __syncthreads();
        #pragma unroll
        for (int st = 128; st > 0; st >>= 1) {
            if (tid < st) red[tid] += red[tid + st];
            __syncthreads();
        }
        if (tid == 0) g_part[s * NCTAS + blockIdx.x] = red[0];
        __syncthreads();
    }

    // ---- quantized output: out[b][d][t] = x - R_final ----
    #pragma unroll
    for (int it = 0; it < 64; it++) {
        int idx = it * 256 + tid;
        int d = idx >> 7, tl = idx & 127;
        size_t go = ((size_t)b * Dx + d) * Tx + t0 + tl;
        out[go] = x[go] - R_sm[tl * 132 + d];
    }
}

// ---------------------------------------------------------------------------
// bw + penalty
// ---------------------------------------------------------------------------
__global__ void pack_kernel(float* __restrict__ out) {
    __shared__ float red[256];
    const size_t COFF = (size_t)Bx * Dx * Tx + (size_t)Sx * ROWS;
    int tid = threadIdx.x;
    float s = 0.0f;
    for (int i = tid; i < Sx * NCTAS; i += 256) s += g_part[i];
    red[tid] = s;
    __syncthreads();
    #pragma unroll
    for (int st = 128; st > 0; st >>= 1) {
        if (tid < st) red[tid] += red[tid + st];
        __syncthreads();
    }
    if (tid == 0) {
        out[COFF + 0] = 6000.0f;   // 8 * log2(1024) * 75
        out[COFF + 1] = red[0] / ((float)Sx * (float)ROWS * (float)Dx);
    }
}

extern "C" void kernel_launch(void* const* d_in, const int* in_sizes, int n_in,
                              void* d_out, int out_size) {
    const float* x  = (const float*)d_in[0];
    const float* cb = (const float*)d_in[1];
    float* out = (float*)d_out;

    cudaFuncSetAttribute(rvq_kernel, cudaFuncAttributeMaxDynamicSharedMemorySize,
                         SMEM_TOTAL);

    c2_kernel<<<(Sx * Kx * 32) / 256, 256>>>(cb);
    cvt_cb_kernel<<<(Sx * Kx * 16) / 256, 256>>>(cb);
    rvq_kernel<<<NCTAS, 256, SMEM_TOTAL>>>(x, cb, out);
    pack_kernel<<<1, 256>>>(out);
}

// round 13
// speedup vs baseline: 3.8708x; 1.0579x over previous
#include <cuda_runtime.h>
#include <cuda_fp16.h>
#include <cstdint>

#define Bx 8
#define Dx 128
#define Tx 4096
#define Kx 1024
#define Sx 8
#define ROWS (Bx*Tx)            // 32768
#define NCTAS (ROWS/128)        // 256
#define TAU 0.60f               // rescore window (4-sigma err + 2x key quant)
#define KEYMASK 0xFFFFFC00u
#define C2BIAS 512.0f           // makes folded distances strictly positive

// ---------------- device scratch (no runtime allocation) -------------------
__device__ float g_c2[Sx * Kx];                 // ||c||^2 fp32
__device__ float g_part[Sx * NCTAS];            // commit partials
// fp16 B fragment bundles: per (s,nt) tile: 128 rows x 256B (validated layout)
__device__ uint4 g_cbB[(size_t)Sx * Kx * 16];   // 2 MB

// ---------------- SMEM layout (byte offsets) --------------------------------
#define BROW    288           // padded B row stride (conflict-free LDS.64)
#define BBUF_H  18432         // 64 rows * 288  (half-tile buffer)
#define SMB_B   0             // 2 x BBUF_H = 36864
#define SMB_R   36864         // 128 x 132 fp32 = 67584
#define SMB_C2  104448        // 1024 fp32 = 4096  (BIASED by C2BIAS)
#define SMB_K1  108544        // 128 u32
#define SMB_K2  109056        // 128 u32
#define SMB_K3  109568        // 128 u32
#define SMB_D2  110080        // 128 fp32 (half-1 rescore distance)
#define SMB_I2  110592        // 128 int  (half-1 rescore index)
#define SMB_IDX 111104        // 128 int
#define SMB_RED 111616        // 8 fp32 (per-warp commit partials)
#define SMEM_TOTAL 111744     // fits 2 CTAs/SM

// ---------------- helpers ----------------------------------------------------
__device__ __forceinline__ uint32_t pack_f16(float a, float b) {
    __half2 h = __floats2half2_rn(a, b);
    return *reinterpret_cast<uint32_t*>(&h);
}
__device__ __forceinline__ uint32_t smem_u32(const void* p) {
    uint32_t a;
    asm("{ .reg .u64 t; cvta.to.shared.u64 t, %1; cvt.u32.u64 %0, t; }" : "=r"(a) : "l"(p));
    return a;
}

// m16n8k16 row.col fp16 MMA, fp32 accumulate (in place)
__device__ __forceinline__ void mma_f16(float* c, const uint32_t* a,
                                        uint32_t b0, uint32_t b1) {
    asm volatile(
        "mma.sync.aligned.m16n8k16.row.col.f32.f16.f16.f32 "
        "{%0,%1,%2,%3}, {%4,%5,%6,%7}, {%8,%9}, {%0,%1,%2,%3};"
        : "+f"(c[0]), "+f"(c[1]), "+f"(c[2]), "+f"(c[3])
        : "r"(a[0]), "r"(a[1]), "r"(a[2]), "r"(a[3]), "r"(b0), "r"(b1));
}

#define CP_ASYNC16(dst, src) \
    asm volatile("cp.async.cg.shared.global [%0], [%1], 16;" :: "r"(dst), "l"(src))
#define CP_COMMIT() asm volatile("cp.async.commit_group;" ::: "memory")
#define CP_WAIT0()  asm volatile("cp.async.wait_group 0;" ::: "memory")

// key for strictly-POSITIVE biased distances: raw float bits are order-
// preserving; low 10 mantissa bits carry the candidate index.
__device__ __forceinline__ uint32_t mk_key(float d, int n) {
    return (__float_as_uint(d) & KEYMASK) | (uint32_t)n;
}
__device__ __forceinline__ float key_to_f(uint32_t k) {
    return __uint_as_float(k & KEYMASK);   // biased value; bias cancels in gaps
}
// branchless sorted top-3 insert (ascending keys)
__device__ __forceinline__ void ins3(uint32_t& v1, uint32_t& v2, uint32_t& v3,
                                     uint32_t k) {
    uint32_t c  = v3 < k ? v3 : k;        // drop max(v3, k)
    uint32_t lo = v2 < c ? v2 : c;
    uint32_t hi = v2 < c ? c : v2;
    v3 = hi;
    uint32_t n1 = v1 < lo ? v1 : lo;
    v2 = v1 < lo ? lo : v1;
    v1 = n1;
}

// exact biased fp32 distance of SMEM residual row to codeword k (4-way ILP)
__device__ __forceinline__ float exact_dist(const float* R_row, const float* cbk,
                                            float c2biased) {
    const float4* rr4 = (const float4*)R_row;
    const float4* cp4 = (const float4*)cbk;
    float s0 = 0.f, s1 = 0.f, s2 = 0.f, s3 = 0.f;
    #pragma unroll
    for (int q = 0; q < 32; q += 4) {
        float4 a0 = rr4[q],     u0 = cp4[q];
        float4 a1 = rr4[q + 1], u1 = cp4[q + 1];
        float4 a2 = rr4[q + 2], u2 = cp4[q + 2];
        float4 a3 = rr4[q + 3], u3 = cp4[q + 3];
        s0 = fmaf(a0.x, u0.x, s0); s1 = fmaf(a0.y, u0.y, s1);
        s2 = fmaf(a0.z, u0.z, s2); s3 = fmaf(a0.w, u0.w, s3);
        s0 = fmaf(a1.x, u1.x, s0); s1 = fmaf(a1.y, u1.y, s1);
        s2 = fmaf(a1.z, u1.z, s2); s3 = fmaf(a1.w, u1.w, s3);
        s0 = fmaf(a2.x, u2.x, s0); s1 = fmaf(a2.y, u2.y, s1);
        s2 = fmaf(a2.z, u2.z, s2); s3 = fmaf(a2.w, u2.w, s3);
        s0 = fmaf(a3.x, u3.x, s0); s1 = fmaf(a3.y, u3.y, s1);
        s2 = fmaf(a3.z, u3.z, s2); s3 = fmaf(a3.w, u3.w, s3);
    }
    return fmaf(-2.0f, (s0 + s1) + (s2 + s3), c2biased);
}

// ---------------------------------------------------------------------------
// ||c||^2 for all stages: one warp per codeword.
// ---------------------------------------------------------------------------
__global__ void c2_kernel(const float* __restrict__ cb) {
    int w    = (blockIdx.x * blockDim.x + threadIdx.x) >> 5;
    int lane = threadIdx.x & 31;
    if (w >= Sx * Kx) return;
    float4 v = reinterpret_cast<const float4*>(cb)[(size_t)w * 32 + lane];
    float p = v.x * v.x + v.y * v.y + v.z * v.z + v.w * v.w;
    #pragma unroll
    for (int o = 16; o; o >>= 1) p += __shfl_down_sync(0xFFFFFFFFu, p, o);
    if (lane == 0) g_c2[w] = p;
}

// ---------------------------------------------------------------------------
// Codebooks -> fp16 fragment chunks (layout validated rounds 8-12).
// ---------------------------------------------------------------------------
__global__ void cvt_cb_kernel(const float* __restrict__ cb) {
    int idx = blockIdx.x * 256 + threadIdx.x;
    if (idx >= Sx * Kx * 16) return;
    int tp = idx & 1;
    int kc = (idx >> 1) & 7;
    int gk = idx >> 4;                           // s*Kx + n
    const float* row = cb + (size_t)gk * Dx + kc * 16 + 4 * tp;
    uint4 v;
    v.x = pack_f16(row[0], row[1]);
    v.y = pack_f16(row[8], row[9]);
    v.z = pack_f16(row[2], row[3]);
    v.w = pack_f16(row[10], row[11]);
    int s = gk >> 10, n = gk & 1023;
    size_t dst = ((size_t)(s * 8 + (n >> 7)) * 128 + (n & 127)) * 16 + kc * 2 + tp;
    g_cbB[dst] = v;
}

// ---------------------------------------------------------------------------
// Fused 8-stage RVQ: 1-pass fp16 mma (nb-outer, per-nb fold) + biased-key
// top-3 + parallel exact rescore.
// grid = 256 CTAs x 256 threads, 2 CTAs/SM; warp w owns rows w*16..w*16+15.
// ---------------------------------------------------------------------------
__global__ void __launch_bounds__(256, 2)
rvq_kernel(const float* __restrict__ x, const float* __restrict__ cb,
           float* __restrict__ out) {
    extern __shared__ char sm[];
    float*    R_sm = (float*)(sm + SMB_R);
    float*    c2s  = (float*)(sm + SMB_C2);
    uint32_t* k1s  = (uint32_t*)(sm + SMB_K1);
    uint32_t* k2s  = (uint32_t*)(sm + SMB_K2);
    uint32_t* k3s  = (uint32_t*)(sm + SMB_K3);
    float*    d2s  = (float*)(sm + SMB_D2);
    int*      i2s  = (int*)(sm + SMB_I2);
    int*      sidx = (int*)(sm + SMB_IDX);
    float*    red  = (float*)(sm + SMB_RED);
    const uint32_t smb = smem_u32(sm);

    const int tid  = threadIdx.x;
    const int wid  = tid >> 5;
    const int lane = tid & 31;
    const int g    = lane >> 2;
    const int tig  = lane & 3;
    const int wrow = wid * 16;
    const int row0 = blockIdx.x * 128;
    const int b    = row0 >> 12;
    const int t0   = row0 & (Tx - 1);
    const size_t QOFF = (size_t)Bx * Dx * Tx;

    // ---- initial residual: R[t][d] = x[b][d][t0+t] (coalesced over t) ----
    #pragma unroll
    for (int it = 0; it < 64; it++) {
        int idx = it * 256 + tid;
        int d = idx >> 7, tl = idx & 127;
        R_sm[tl * 132 + d] = x[((size_t)b * Dx + d) * Tx + t0 + tl];
    }
    __syncthreads();

    #pragma unroll 1
    for (int s = 0; s < Sx; s++) {
        // ---- prefetch B half-tile 0 of this stage ----
        {
            const char* src = (const char*)(g_cbB + (size_t)(s * 8) * 2048);
            #pragma unroll
            for (int it = 0; it < 4; it++) {
                int idx = it * 256 + tid;
                int r = idx >> 4, c = idx & 15;
                CP_ASYNC16(smb + SMB_B + r * BROW + c * 16, src + r * 256 + c * 16);
            }
            CP_COMMIT();
        }

        // stage BIASED c2 into SMEM (guarantees positive folded distances)
        for (int i = tid; i < Kx; i += 256) c2s[i] = g_c2[s * Kx + i] + C2BIAS;

        // ---- A fragments (fp16) for this warp's 16 rows, reused all tiles ----
        uint32_t ah[8][4];
        #pragma unroll
        for (int kc = 0; kc < 8; kc++) {
            const float* base = &R_sm[(wrow + g) * 132 + kc * 16 + 2 * tig];
            float2 p0 = *(const float2*)(base);
            float2 p1 = *(const float2*)(base + 8 * 132);
            float2 p2 = *(const float2*)(base + 8);
            float2 p3 = *(const float2*)(base + 8 * 132 + 8);
            ah[kc][0] = pack_f16(p0.x, p0.y);
            ah[kc][1] = pack_f16(p1.x, p1.y);
            ah[kc][2] = pack_f16(p2.x, p2.y);
            ah[kc][3] = pack_f16(p3.x, p3.y);
        }

        // per-thread packed-key top-3 for two row-slots
        uint32_t ka1 = 0xFFFFFFFFu, ka2 = 0xFFFFFFFFu, ka3 = 0xFFFFFFFFu;
        uint32_t kb1 = 0xFFFFFFFFu, kb2 = 0xFFFFFFFFu, kb3 = 0xFFFFFFFFu;

        // ---- 16 half-tiles of 64 codewords, ping-pong buffered ----
        #pragma unroll 1
        for (int h = 0; h < 16; h++) {
            CP_WAIT0();
            __syncthreads();                 // half(h) visible; other buf free
            if (h < 15) {                    // prefetch h+1 into other buffer
                const char* src = (const char*)(g_cbB + (size_t)(s * 8) * 2048)
                                + (h + 1) * 16384;
                uint32_t dst = smb + SMB_B + ((h + 1) & 1) * BBUF_H;
                #pragma unroll
                for (int it = 0; it < 4; it++) {
                    int idx = it * 256 + tid;
                    int r = idx >> 4, c = idx & 15;
                    CP_ASYNC16(dst + r * BROW + c * 16, src + r * 256 + c * 16);
                }
                CP_COMMIT();
            }

            const char* bbase = sm + SMB_B + (h & 1) * BBUF_H;

            // nb-outer: 8 MMAs then immediate fold; acc stays 4 regs; the
            // unrolled nb chain lets the scheduler overlap fold ALU with the
            // next nb's tensor work.
            #pragma unroll
            for (int nb = 0; nb < 8; nb++) {
                float a4[4] = {0.f, 0.f, 0.f, 0.f};
                #pragma unroll
                for (int kc = 0; kc < 8; kc++) {
                    uint2 bv = *(const uint2*)(bbase + (nb * 8 + g) * BROW
                                               + kc * 32 + tig * 8);
                    mma_f16(a4, ah[kc], bv.x, bv.y);
                }
                int n0 = h * 64 + nb * 8 + 2 * tig;
                float2 cc = *(const float2*)&c2s[n0];
                float d0 = fmaf(-2.0f, a4[0], cc.x);
                float d1 = fmaf(-2.0f, a4[1], cc.y);
                float d2 = fmaf(-2.0f, a4[2], cc.x);
                float d3 = fmaf(-2.0f, a4[3], cc.y);
                ins3(ka1, ka2, ka3, mk_key(d0, n0));
                ins3(ka1, ka2, ka3, mk_key(d1, n0 + 1));
                ins3(kb1, kb2, kb3, mk_key(d2, n0));
                ins3(kb1, kb2, kb3, mk_key(d3, n0 + 1));
            }
        }

        // ---- merge top-3 across the 4 tig lanes ----
        #pragma unroll
        for (int off = 1; off <= 2; off <<= 1) {
            uint32_t o1 = __shfl_xor_sync(0xFFFFFFFFu, ka1, off);
            uint32_t o2 = __shfl_xor_sync(0xFFFFFFFFu, ka2, off);
            uint32_t o3 = __shfl_xor_sync(0xFFFFFFFFu, ka3, off);
            ins3(ka1, ka2, ka3, o1);
            ins3(ka1, ka2, ka3, o2);
            ins3(ka1, ka2, ka3, o3);
            o1 = __shfl_xor_sync(0xFFFFFFFFu, kb1, off);
            o2 = __shfl_xor_sync(0xFFFFFFFFu, kb2, off);
            o3 = __shfl_xor_sync(0xFFFFFFFFu, kb3, off);
            ins3(kb1, kb2, kb3, o1);
            ins3(kb1, kb2, kb3, o2);
            ins3(kb1, kb2, kb3, o3);
        }
        if (tig == 0) {
            k1s[wrow + g] = ka1; k2s[wrow + g] = ka2; k3s[wrow + g] = ka3;
            k1s[wrow + g + 8] = kb1; k2s[wrow + g + 8] = kb2; k3s[wrow + g + 8] = kb3;
        }
        __syncthreads();

        // ---- parallel exact rescore: half 0 -> cand1 (+cand3), half 1 -> cand2
        {
            const int row  = tid & 127;
            const int half = tid >> 7;
            uint32_t k1 = k1s[row], k2 = k2s[row], k3 = k3s[row];
            float f1 = key_to_f(k1);
            bool trig = (key_to_f(k2) - f1 < TAU);
            bool has3 = trig && (key_to_f(k3) - f1 < TAU);
            float bestd = __int_as_float(0x7F800000);
            int   besti = 0x7fffffff;
            if (trig) {
                int c0 = half ? (int)(k2 & 1023) : (int)(k1 & 1023);
                bestd = exact_dist(&R_sm[row * 132],
                                   cb + ((size_t)s * Kx + c0) * Dx, c2s[c0]);
                besti = c0;
                if (!half && has3) {
                    int c2i = (int)(k3 & 1023);
                    float dx = exact_dist(&R_sm[row * 132],
                                          cb + ((size_t)s * Kx + c2i) * Dx, c2s[c2i]);
                    if (dx < bestd || (dx == bestd && c2i < besti)) {
                        bestd = dx; besti = c2i;
                    }
                }
            }
            if (half) { d2s[row] = bestd; i2s[row] = besti; }
            __syncthreads();
            if (!half) {
                int bi = (int)(k1 & 1023);
                if (trig) {
                    float dB = d2s[row]; int iB = i2s[row];
                    if (dB < bestd || (dB == bestd && iB < besti)) {
                        bestd = dB; besti = iB;
                    }
                    bi = besti;
                }
                sidx[row] = bi;
                out[QOFF + (size_t)s * ROWS + row0 + row] = (float)bi;
            }
        }
        __syncthreads();

        // ---- residual update + commit partial (warp-shuffle reduction) ----
        float cm = 0.0f;
        #pragma unroll
        for (int it = 0; it < 64; it++) {
            int idx = it * 256 + tid;
            int m = idx >> 7, d = idx & 127;
            int k = sidx[m];
            float q  = cb[((size_t)s * Kx + k) * Dx + d];
            float r  = R_sm[m * 132 + d];
            float nr = r - q;
            cm = fmaf(nr, nr, cm);
            R_sm[m * 132 + d] = nr;
        }
        #pragma unroll
        for (int o = 16; o; o >>= 1) cm += __shfl_down_sync(0xFFFFFFFFu, cm, o);
        if (lane == 0) red[wid] = cm;
        __syncthreads();
        if (tid == 0) {
            float ssum = 0.0f;
            #pragma unroll
            for (int w = 0; w < 8; w++) ssum += red[w];
            g_part[s * NCTAS + blockIdx.x] = ssum;
        }
        __syncthreads();
    }

    // ---- quantized output: out[b][d][t] = x - R_final ----
    #pragma unroll
    for (int it = 0; it < 64; it++) {
        int idx = it * 256 + tid;
        int d = idx >> 7, tl = idx & 127;
        size_t go = ((size_t)b * Dx + d) * Tx + t0 + tl;
        out[go] = x[go] - R_sm[tl * 132 + d];
    }
}

// ---------------------------------------------------------------------------
// bw + penalty
// ---------------------------------------------------------------------------
__global__ void pack_kernel(float* __restrict__ out) {
    __shared__ float red[256];
    const size_t COFF = (size_t)Bx * Dx * Tx + (size_t)Sx * ROWS;
    int tid = threadIdx.x;
    float s = 0.0f;
    for (int i = tid; i < Sx * NCTAS; i += 256) s += g_part[i];
    red[tid] = s;
    __syncthreads();
    #pragma unroll
    for (int st = 128; st > 0; st >>= 1) {
        if (tid < st) red[tid] += red[tid + st];
        __syncthreads();
    }
    if (tid == 0) {
        out[COFF + 0] = 6000.0f;   // 8 * log2(1024) * 75
        out[COFF + 1] = red[0] / ((float)Sx * (float)ROWS * (float)Dx);
    }
}

extern "C" void kernel_launch(void* const* d_in, const int* in_sizes, int n_in,
                              void* d_out, int out_size) {
    const float* x  = (const float*)d_in[0];
    const float* cb = (const float*)d_in[1];
    float* out = (float*)d_out;

    cudaFuncSetAttribute(rvq_kernel, cudaFuncAttributeMaxDynamicSharedMemorySize,
                         SMEM_TOTAL);

    c2_kernel<<<(Sx * Kx * 32) / 256, 256>>>(cb);
    cvt_cb_kernel<<<(Sx * Kx * 16) / 256, 256>>>(cb);
    rvq_kernel<<<NCTAS, 256, SMEM_TOTAL>>>(x, cb, out);
    pack_kernel<<<1, 256>>>(out);
}